// round 9
// baseline (speedup 1.0000x reference)
#include <cuda_runtime.h>
#include <cuda_bf16.h>
#include <string.h>

#define N_NODES 100000
#define C 32
#define E_EDGES 3200000
#define SPMM_WARPS 8
#define BITW 3125                               // ceil(N/32), N%32==0

// ---- scratch (no allocations allowed) ----
__device__ float         g_deg[N_NODES];
__device__ float         g_ld[N_NODES];         // fp32 dinv, low 6 mantissa bits = (32|label) if masked else 0
__device__ unsigned      g_bits[BITW];          // mask bitmap, bit n of word n>>5
__device__ __nv_bfloat16 g_qh[N_NODES * C];     // q[c][j] = dinv[c] * p[c][j], bf16
__device__ int2          g_cmp[E_EDGES];        // compacted kept edges: {col | label<<17, f32 vw}
__device__ float         g_H[C * C];            // unnormalized class-compat accumulator
__device__ int           g_mode;                // mask dtype: 0=u8, 1=i32, 2=f32, 3=bf16
__device__ int           g_cnt;                 // kept-edge count

// ---------------------------------------------------------------- init + mask dtype sniffing (block 0, warp 0)
__global__ void k_init(const unsigned char* __restrict__ m) {
    int i = blockIdx.x * blockDim.x + threadIdx.x;
    if (i < N_NODES) g_deg[i] = 1.0f;          // self-loop weight
    if (i < C * C)   g_H[i]   = 0.0f;
    if (i == 0)      g_cnt    = 0;

    if (blockIdx.x == 0 && threadIdx.x < 32) {
        int lane = threadIdx.x;
        int nz0 = 0, nz1 = 0, nz2 = 0, nz3 = 0, c01 = 0, c3F = 0;
        for (int base = 0; base < 4096; base += 32) {
            unsigned char b = m[base + lane];        // (base+lane)&3 == lane&3
            unsigned nzm = __ballot_sync(0xFFFFFFFFu, b != 0);
            unsigned m01 = __ballot_sync(0xFFFFFFFFu, b == 0x01);
            unsigned m3F = __ballot_sync(0xFFFFFFFFu, b == 0x3F);
            nz0 += __popc(nzm & 0x11111111u);
            nz1 += __popc(nzm & 0x22222222u);
            nz2 += __popc(nzm & 0x44444444u);
            nz3 += __popc(nzm & 0x88888888u);
            c01 += __popc(m01);
            c3F += __popc(m3F);
        }
        if (lane == 0) {
            int mode;
            if (nz1 == 0 && nz2 == 0 && nz3 == 0)
                mode = 1;                                        // int32 (0/1, LE)
            else if (c01 == 0 && c3F > 0)
                mode = (nz0 == 0 && nz1 == 0) ? 2 : 3;           // float32 : bf16
            else
                mode = 0;                                        // uint8 bool
            g_mode = mode;
        }
    }
}

__device__ __forceinline__ bool read_mask(const unsigned char* p, int node, int mode) {
    if (mode == 1) return ((const int*)p)[node] != 0;
    if (mode == 2) return ((const float*)p)[node] != 0.0f;
    if (mode == 3) return ((const unsigned short*)p)[node] != 0;
    return p[node] != 0;
}

// ---------------------------------------------------------------- degree (vectorized)
__global__ void k_deg(const int4* __restrict__ row4, const float4* __restrict__ w4) {
    int e = blockIdx.x * blockDim.x + threadIdx.x;
    if (e < E_EDGES / 4) {
        int4   r = row4[e];
        float4 w = w4[e];
        atomicAdd(&g_deg[r.x], w.x);
        atomicAdd(&g_deg[r.y], w.y);
        atomicAdd(&g_deg[r.z], w.z);
        atomicAdd(&g_deg[r.w], w.w);
    }
}

// ---------------------------------------------------------------- per-node: softmax / mask / dinv / q / self-loop diag
// Register-direct, thread-per-node. Also emits the mask bitmap (1 ballot/warp).
__global__ __launch_bounds__(256) void k_node(const float* __restrict__ x,
                                              const float* __restrict__ y,
                                              const unsigned char* __restrict__ mask) {
    __shared__ float sdiag[C];
    int tid = threadIdx.x;
    if (tid < C) sdiag[tid] = 0.0f;
    __syncthreads();

    int node = blockIdx.x * 256 + tid;
    int mode = g_mode;
    bool msk = (node < N_NODES) ? read_mask(mask, node, mode) : false;

    // bitmap word per warp (nodes are 32-aligned per warp)
    unsigned word = __ballot_sync(0xFFFFFFFFu, msk);
    if ((tid & 31) == 0 && (node >> 5) < BITW) g_bits[node >> 5] = word;

    if (node < N_NODES) {
        float dinv = rsqrtf(g_deg[node]);        // deg >= 1 always
        unsigned packed[16];
        unsigned enc;

        if (msk) {
            // label = argmax of one-hot row (only masked nodes need y)
            const float4* yr = (const float4*)(y + (size_t)node * C);
            int lab = 0;
            #pragma unroll
            for (int i = 0; i < 8; i++) {
                float4 q = yr[i];
                lab = (q.x > 0.5f) ? 4 * i     : lab;
                lab = (q.y > 0.5f) ? 4 * i + 1 : lab;
                lab = (q.z > 0.5f) ? 4 * i + 2 : lab;
                lab = (q.w > 0.5f) ? 4 * i + 3 : lab;
            }
            __nv_bfloat16 h = __float2bfloat16(dinv);
            unsigned hb;
            { unsigned short s; memcpy(&s, &h, 2); hb = s; }
            #pragma unroll
            for (int i = 0; i < 16; i++) {
                unsigned lo = (lab == 2 * i)     ? hb : 0u;
                unsigned hi = (lab == 2 * i + 1) ? hb : 0u;
                packed[i] = lo | (hi << 16);
            }
            atomicAdd(&sdiag[lab], dinv * dinv);             // self-loop diag
            enc = (__float_as_uint(dinv) & ~63u) | 32u | (unsigned)lab;
        } else {
            const float4* xr = (const float4*)(x + (size_t)node * C);
            float v[32];
            #pragma unroll
            for (int i = 0; i < 8; i++) {
                float4 q = xr[i];
                v[4*i] = q.x; v[4*i+1] = q.y; v[4*i+2] = q.z; v[4*i+3] = q.w;
            }
            float m0 = v[0], m1 = v[1], m2 = v[2], m3 = v[3];
            #pragma unroll
            for (int r = 4; r < 32; r += 4) {
                m0 = fmaxf(m0, v[r]); m1 = fmaxf(m1, v[r+1]);
                m2 = fmaxf(m2, v[r+2]); m3 = fmaxf(m3, v[r+3]);
            }
            float mx = fmaxf(fmaxf(m0, m1), fmaxf(m2, m3));
            float a0 = 0.f, a1 = 0.f, a2 = 0.f, a3 = 0.f;
            #pragma unroll
            for (int r = 0; r < 32; r += 4) {
                v[r]   = __expf(v[r]   - mx); a0 += v[r];
                v[r+1] = __expf(v[r+1] - mx); a1 += v[r+1];
                v[r+2] = __expf(v[r+2] - mx); a2 += v[r+2];
                v[r+3] = __expf(v[r+3] - mx); a3 += v[r+3];
            }
            float f = dinv / ((a0 + a1) + (a2 + a3));
            #pragma unroll
            for (int i = 0; i < 16; i++) {
                __nv_bfloat162 hh = __float22bfloat162_rn(make_float2(v[2*i] * f, v[2*i+1] * f));
                memcpy(&packed[i], &hh, 4);
            }
            enc = __float_as_uint(dinv) & ~63u;
        }

        uint4* dst = (uint4*)(g_qh + (size_t)node * C);
        dst[0] = make_uint4(packed[0],  packed[1],  packed[2],  packed[3]);
        dst[1] = make_uint4(packed[4],  packed[5],  packed[6],  packed[7]);
        dst[2] = make_uint4(packed[8],  packed[9],  packed[10], packed[11]);
        dst[3] = make_uint4(packed[12], packed[13], packed[14], packed[15]);
        g_ld[node] = __uint_as_float(enc);
    }
    __syncthreads();
    if (tid < C && sdiag[tid] != 0.0f) atomicAdd(&g_H[tid * C + tid], sdiag[tid]);
}

// ---------------------------------------------------------------- compaction: smem-bitmap prefilter, gather g_ld only for kept
__global__ __launch_bounds__(256) void k_compact(const int4* __restrict__ row4,
                                                 const int4* __restrict__ col4,
                                                 const float4* __restrict__ w4) {
    __shared__ unsigned sbits[BITW + 3];
    int tid  = threadIdx.x;
    int lane = tid & 31;
    for (int i = tid; i < BITW; i += 256) sbits[i] = g_bits[i];
    __syncthreads();

    for (int i = blockIdx.x * 256 + tid; i < E_EDGES / 4; i += gridDim.x * 256) {
        int4 rr = row4[i];

        bool k0 = (sbits[rr.x >> 5] >> (rr.x & 31)) & 1u;
        bool k1 = (sbits[rr.y >> 5] >> (rr.y & 31)) & 1u;
        bool k2 = (sbits[rr.z >> 5] >> (rr.z & 31)) & 1u;
        bool k3 = (sbits[rr.w >> 5] >> (rr.w & 31)) & 1u;

        float d0 = 0.f, d1 = 0.f, d2 = 0.f, d3 = 0.f;
        if (k0) d0 = g_ld[rr.x];
        if (k1) d1 = g_ld[rr.y];
        if (k2) d2 = g_ld[rr.z];
        if (k3) d3 = g_ld[rr.w];

        int cnt = (int)k0 + (int)k1 + (int)k2 + (int)k3;
        // inclusive warp scan
        int ofs = cnt;
        #pragma unroll
        for (int d = 1; d < 32; d <<= 1) {
            int n = __shfl_up_sync(0xFFFFFFFFu, ofs, d);
            if (lane >= d) ofs += n;
        }
        int total = __shfl_sync(0xFFFFFFFFu, ofs, 31);
        int basep = 0;
        if (lane == 31 && total) basep = atomicAdd(&g_cnt, total);
        basep = __shfl_sync(0xFFFFFFFFu, basep, 31);
        int p = basep + ofs - cnt;

        if (cnt) {
            int4   cc = col4[i];
            float4 ww = w4[i];
            unsigned t0 = __float_as_uint(d0) & 63u;
            unsigned t1 = __float_as_uint(d1) & 63u;
            unsigned t2 = __float_as_uint(d2) & 63u;
            unsigned t3 = __float_as_uint(d3) & 63u;
            if (k0) g_cmp[p++] = make_int2(cc.x | (int)((t0 - 32u) << 17), __float_as_int(d0 * ww.x));
            if (k1) g_cmp[p++] = make_int2(cc.y | (int)((t1 - 32u) << 17), __float_as_int(d1 * ww.y));
            if (k2) g_cmp[p++] = make_int2(cc.z | (int)((t2 - 32u) << 17), __float_as_int(d2 * ww.z));
            if (k3) g_cmp[p++] = make_int2(cc.w | (int)((t3 - 32u) << 17), __float_as_int(d3 * ww.w));
        }
    }
}

// ---------------------------------------------------------------- dense sweep -> 32x32 tile
// Broadcast model: one edge per inner step; lane j sole owner of column j -> no atomics.
__global__ __launch_bounds__(256) void k_spmm() {
    __shared__ float Hs[SPMM_WARPS][C * C];
    int lane = threadIdx.x & 31;
    int wid  = threadIdx.x >> 5;
    float* Hw = Hs[wid];
    for (int i = lane; i < C * C; i += 32) Hw[i] = 0.0f;
    __syncwarp();

    int total = g_cnt;
    int gw = blockIdx.x * SPMM_WARPS + wid;
    int nw = gridDim.x * SPMM_WARPS;

    for (int base = gw * 32; base < total; base += nw * 32) {
        int e = base + lane;
        int2 ent = (e < total) ? g_cmp[e] : make_int2(0, 0);
        if (base + 32 <= total) {
            #pragma unroll
            for (int k = 0; k < 32; k++) {
                int   pk = __shfl_sync(0xFFFFFFFFu, ent.x, k);
                float v  = __uint_as_float(__shfl_sync(0xFFFFFFFFu, ent.y, k));
                int c = pk & 0x1FFFF;
                int l = pk >> 17;
                float qv = __bfloat162float(g_qh[c * C + lane]);
                Hw[l * C + lane] += v * qv;
            }
        } else {
            int cnt = total - base;
            for (int k = 0; k < cnt; k++) {
                int   pk = __shfl_sync(0xFFFFFFFFu, ent.x, k);
                float v  = __uint_as_float(__shfl_sync(0xFFFFFFFFu, ent.y, k));
                int c = pk & 0x1FFFF;
                int l = pk >> 17;
                float qv = __bfloat162float(g_qh[c * C + lane]);
                Hw[l * C + lane] += v * qv;
            }
        }
    }

    __syncthreads();
    for (int i = threadIdx.x; i < C * C; i += blockDim.x) {
        float s = 0.0f;
        #pragma unroll
        for (int wg = 0; wg < SPMM_WARPS; wg++) s += Hs[wg][i];
        atomicAdd(&g_H[i], s);
    }
}

// ---------------------------------------------------------------- Sinkhorn: tree sums, 2 syncwarps/iter
__global__ void k_sinkhorn(float* __restrict__ out) {
    __shared__ float ss[C * 33];
    __shared__ float sinv[C];
    int t = threadIdx.x;   // thread t holds column t

    float v[C];
    #pragma unroll
    for (int r = 0; r < C; r++) v[r] = g_H[r * C + t];

    for (int it = 0; it < 3000; it++) {
        // column normalize (local, tree sum)
        float a0 = 0.f, a1 = 0.f, a2 = 0.f, a3 = 0.f;
        #pragma unroll
        for (int r = 0; r < C; r += 4) { a0 += v[r]; a1 += v[r+1]; a2 += v[r+2]; a3 += v[r+3]; }
        float s = (a0 + a1) + (a2 + a3);
        float ic = 1.0f / s;
        #pragma unroll
        for (int r = 0; r < C; r++) { v[r] *= ic; ss[r * 33 + t] = v[r]; }
        __syncwarp();

        // row sum of row t (conflict-free), publish reciprocal
        float b0 = 0.f, b1 = 0.f, b2 = 0.f, b3 = 0.f;
        #pragma unroll
        for (int cc = 0; cc < C; cc += 4) {
            b0 += ss[t * 33 + cc];     b1 += ss[t * 33 + cc + 1];
            b2 += ss[t * 33 + cc + 2]; b3 += ss[t * 33 + cc + 3];
        }
        float s2 = (b0 + b1) + (b2 + b3);
        sinv[t] = 1.0f / s2;
        __syncwarp();

        // row normalize (broadcast reads of sinv)
        #pragma unroll
        for (int r = 0; r < C; r++) v[r] *= sinv[r];

        // both scale factors -> 1 at the fixed point; check every 2 iters
        if (it & 1) {
            float dev = fmaxf(fabsf(s - 1.0f), fabsf(s2 - 1.0f));
            if (it >= 5 && __all_sync(0xFFFFFFFFu, dev < 1e-4f)) break;
        }
    }

    #pragma unroll
    for (int r = 0; r < C; r++) out[r * C + t] = v[r];
}

// ---------------------------------------------------------------- launch
extern "C" void kernel_launch(void* const* d_in, const int* in_sizes, int n_in,
                              void* d_out, int out_size) {
    const int*           ei   = (const int*)d_in[0];      // (2, E): rows then cols
    const float*         ew   = (const float*)d_in[1];    // (E,)
    const float*         x    = (const float*)d_in[2];    // (N, C)
    const float*         y    = (const float*)d_in[3];    // (N, C) one-hot
    const unsigned char* mask = (const unsigned char*)d_in[4];  // (N,) dtype sniffed

    const int* row = ei;
    const int* col = ei + E_EDGES;

    k_init<<<(N_NODES + 255) / 256, 256>>>(mask);
    k_deg<<<(E_EDGES / 4 + 255) / 256, 256>>>((const int4*)row, (const float4*)ew);
    k_node<<<(N_NODES + 255) / 256, 256>>>(x, y, mask);
    k_compact<<<1184, 256>>>((const int4*)row, (const int4*)col, (const float4*)ew);
    k_spmm<<<592, 256>>>();
    k_sinkhorn<<<1, 32>>>((float*)d_out);
}

// round 10
// speedup vs baseline: 1.0006x; 1.0006x over previous
#include <cuda_runtime.h>
#include <cuda_bf16.h>
#include <string.h>

#define N_NODES 100000
#define C 32
#define E_EDGES 3200000
#define SPMM_WARPS 8

// ---- scratch (no allocations allowed) ----
__device__ float         g_deg[N_NODES];
__device__ float         g_ld[N_NODES];         // fp32 dinv, low 6 mantissa bits = (32|label) if masked else 0
__device__ __nv_bfloat16 g_qh[N_NODES * C];     // q[c][j] = dinv[c] * p[c][j], bf16
__device__ float         g_H[C * C];            // unnormalized class-compat accumulator
__device__ int           g_mode;                // mask dtype: 0=u8, 1=i32, 2=f32, 3=bf16

// ---------------------------------------------------------------- init + mask dtype sniffing (block 0, warp 0)
__global__ void k_init(const unsigned char* __restrict__ m) {
    int i = blockIdx.x * blockDim.x + threadIdx.x;
    if (i < N_NODES) g_deg[i] = 1.0f;          // self-loop weight
    if (i < C * C)   g_H[i]   = 0.0f;

    if (blockIdx.x == 0 && threadIdx.x < 32) {
        int lane = threadIdx.x;
        int nz0 = 0, nz1 = 0, nz2 = 0, nz3 = 0, c01 = 0, c3F = 0;
        for (int base = 0; base < 4096; base += 32) {
            unsigned char b = m[base + lane];        // (base+lane)&3 == lane&3
            unsigned nzm = __ballot_sync(0xFFFFFFFFu, b != 0);
            unsigned m01 = __ballot_sync(0xFFFFFFFFu, b == 0x01);
            unsigned m3F = __ballot_sync(0xFFFFFFFFu, b == 0x3F);
            nz0 += __popc(nzm & 0x11111111u);
            nz1 += __popc(nzm & 0x22222222u);
            nz2 += __popc(nzm & 0x44444444u);
            nz3 += __popc(nzm & 0x88888888u);
            c01 += __popc(m01);
            c3F += __popc(m3F);
        }
        if (lane == 0) {
            int mode;
            if (nz1 == 0 && nz2 == 0 && nz3 == 0)
                mode = 1;                                        // int32 (0/1, LE)
            else if (c01 == 0 && c3F > 0)
                mode = (nz0 == 0 && nz1 == 0) ? 2 : 3;           // float32 : bf16
            else
                mode = 0;                                        // uint8 bool
            g_mode = mode;
        }
    }
}

__device__ __forceinline__ bool read_mask(const unsigned char* p, int node, int mode) {
    if (mode == 1) return ((const int*)p)[node] != 0;
    if (mode == 2) return ((const float*)p)[node] != 0.0f;
    if (mode == 3) return ((const unsigned short*)p)[node] != 0;
    return p[node] != 0;
}

// ---------------------------------------------------------------- degree (vectorized)
__global__ void k_deg(const int4* __restrict__ row4, const float4* __restrict__ w4) {
    int e = blockIdx.x * blockDim.x + threadIdx.x;
    if (e < E_EDGES / 4) {
        int4   r = row4[e];
        float4 w = w4[e];
        atomicAdd(&g_deg[r.x], w.x);
        atomicAdd(&g_deg[r.y], w.y);
        atomicAdd(&g_deg[r.z], w.z);
        atomicAdd(&g_deg[r.w], w.w);
    }
}

// ---------------------------------------------------------------- per-node: softmax / mask / dinv / q / self-loop diag
// Register-direct, thread-per-node. Each thread owns its 128B row (full-sector loads).
__global__ __launch_bounds__(256) void k_node(const float* __restrict__ x,
                                              const float* __restrict__ y,
                                              const unsigned char* __restrict__ mask) {
    __shared__ float sdiag[C];
    int tid = threadIdx.x;
    if (tid < C) sdiag[tid] = 0.0f;
    __syncthreads();

    int node = blockIdx.x * 256 + tid;
    if (node < N_NODES) {
        int  mode = g_mode;
        bool msk  = read_mask(mask, node, mode);
        float dinv = rsqrtf(g_deg[node]);        // deg >= 1 always
        unsigned packed[16];
        unsigned enc;

        if (msk) {
            // label = argmax of one-hot row (only masked nodes need y)
            const float4* yr = (const float4*)(y + (size_t)node * C);
            int lab = 0;
            #pragma unroll
            for (int i = 0; i < 8; i++) {
                float4 q = yr[i];
                lab = (q.x > 0.5f) ? 4 * i     : lab;
                lab = (q.y > 0.5f) ? 4 * i + 1 : lab;
                lab = (q.z > 0.5f) ? 4 * i + 2 : lab;
                lab = (q.w > 0.5f) ? 4 * i + 3 : lab;
            }
            __nv_bfloat16 h = __float2bfloat16(dinv);
            unsigned hb;
            { unsigned short s; memcpy(&s, &h, 2); hb = s; }
            #pragma unroll
            for (int i = 0; i < 16; i++) {
                unsigned lo = (lab == 2 * i)     ? hb : 0u;
                unsigned hi = (lab == 2 * i + 1) ? hb : 0u;
                packed[i] = lo | (hi << 16);
            }
            atomicAdd(&sdiag[lab], dinv * dinv);             // self-loop diag
            enc = (__float_as_uint(dinv) & ~63u) | 32u | (unsigned)lab;
        } else {
            const float4* xr = (const float4*)(x + (size_t)node * C);
            float v[32];
            #pragma unroll
            for (int i = 0; i < 8; i++) {
                float4 q = xr[i];
                v[4*i] = q.x; v[4*i+1] = q.y; v[4*i+2] = q.z; v[4*i+3] = q.w;
            }
            float m0 = v[0], m1 = v[1], m2 = v[2], m3 = v[3];
            #pragma unroll
            for (int r = 4; r < 32; r += 4) {
                m0 = fmaxf(m0, v[r]); m1 = fmaxf(m1, v[r+1]);
                m2 = fmaxf(m2, v[r+2]); m3 = fmaxf(m3, v[r+3]);
            }
            float mx = fmaxf(fmaxf(m0, m1), fmaxf(m2, m3));
            float a0 = 0.f, a1 = 0.f, a2 = 0.f, a3 = 0.f;
            #pragma unroll
            for (int r = 0; r < 32; r += 4) {
                v[r]   = __expf(v[r]   - mx); a0 += v[r];
                v[r+1] = __expf(v[r+1] - mx); a1 += v[r+1];
                v[r+2] = __expf(v[r+2] - mx); a2 += v[r+2];
                v[r+3] = __expf(v[r+3] - mx); a3 += v[r+3];
            }
            float f = dinv / ((a0 + a1) + (a2 + a3));
            #pragma unroll
            for (int i = 0; i < 16; i++) {
                __nv_bfloat162 hh = __float22bfloat162_rn(make_float2(v[2*i] * f, v[2*i+1] * f));
                memcpy(&packed[i], &hh, 4);
            }
            enc = __float_as_uint(dinv) & ~63u;
        }

        uint4* dst = (uint4*)(g_qh + (size_t)node * C);
        dst[0] = make_uint4(packed[0],  packed[1],  packed[2],  packed[3]);
        dst[1] = make_uint4(packed[4],  packed[5],  packed[6],  packed[7]);
        dst[2] = make_uint4(packed[8],  packed[9],  packed[10], packed[11]);
        dst[3] = make_uint4(packed[12], packed[13], packed[14], packed[15]);
        g_ld[node] = __uint_as_float(enc);
    }
    __syncthreads();
    if (tid < C && sdiag[tid] != 0.0f) atomicAdd(&g_H[tid * C + tid], sdiag[tid]);
}

// ---------------------------------------------------------------- fused sweep: gather node info (MLP=4) + accumulate H
// Per component: ballot kept lanes, 4-wide ffs extraction, broadcast edge, lane j owns column j.
__device__ __forceinline__ void sweep_comp(bool k, int pk, float v, float* __restrict__ Hw,
                                           int lane, const __nv_bfloat16* __restrict__ qh) {
    unsigned keep = __ballot_sync(0xFFFFFFFFu, k);
    while (keep) {
        int k0 = __ffs(keep) - 1; keep &= keep - 1;
        bool h1 = keep != 0; int k1 = k0;
        if (h1) { k1 = __ffs(keep) - 1; keep &= keep - 1; }
        bool h2 = keep != 0; int k2 = k0;
        if (h2) { k2 = __ffs(keep) - 1; keep &= keep - 1; }
        bool h3 = keep != 0; int k3 = k0;
        if (h3) { k3 = __ffs(keep) - 1; keep &= keep - 1; }

        int   p0 = __shfl_sync(0xFFFFFFFFu, pk, k0);
        float v0 = __shfl_sync(0xFFFFFFFFu, v,  k0);
        int   p1 = __shfl_sync(0xFFFFFFFFu, pk, k1);
        float v1 = __shfl_sync(0xFFFFFFFFu, v,  k1);
        int   p2 = __shfl_sync(0xFFFFFFFFu, pk, k2);
        float v2 = __shfl_sync(0xFFFFFFFFu, v,  k2);
        int   p3 = __shfl_sync(0xFFFFFFFFu, pk, k3);
        float v3 = __shfl_sync(0xFFFFFFFFu, v,  k3);

        float q0 =      __bfloat162float(qh[(p0 & 0x1FFFF) * C + lane]);
        float q1 = h1 ? __bfloat162float(qh[(p1 & 0x1FFFF) * C + lane]) : 0.0f;
        float q2 = h2 ? __bfloat162float(qh[(p2 & 0x1FFFF) * C + lane]) : 0.0f;
        float q3 = h3 ? __bfloat162float(qh[(p3 & 0x1FFFF) * C + lane]) : 0.0f;

        Hw[(p0 >> 17) * C + lane] += v0 * q0;
        if (h1) Hw[(p1 >> 17) * C + lane] += v1 * q1;
        if (h2) Hw[(p2 >> 17) * C + lane] += v2 * q2;
        if (h3) Hw[(p3 >> 17) * C + lane] += v3 * q3;
    }
}

__global__ __launch_bounds__(256) void k_sweep(const int4* __restrict__ row4,
                                               const int4* __restrict__ col4,
                                               const float4* __restrict__ w4) {
    __shared__ float Hs[SPMM_WARPS][C * C];
    int tid  = threadIdx.x;
    int lane = tid & 31;
    int wid  = tid >> 5;
    float* Hw = Hs[wid];
    for (int i = lane; i < C * C; i += 32) Hw[i] = 0.0f;
    __syncwarp();

    for (int i = blockIdx.x * 256 + tid; i < E_EDGES / 4; i += gridDim.x * 256) {
        int4 rr = row4[i];
        // front-batched MLP=4 gathers (R8-proven structure)
        float d0 = g_ld[rr.x];
        float d1 = g_ld[rr.y];
        float d2 = g_ld[rr.z];
        float d3 = g_ld[rr.w];
        int4   cc = col4[i];
        float4 ww = w4[i];

        unsigned t0 = __float_as_uint(d0) & 63u;
        unsigned t1 = __float_as_uint(d1) & 63u;
        unsigned t2 = __float_as_uint(d2) & 63u;
        unsigned t3 = __float_as_uint(d3) & 63u;

        sweep_comp(t0 >= 32u, cc.x | (int)((t0 - 32u) << 17), d0 * ww.x, Hw, lane, g_qh);
        sweep_comp(t1 >= 32u, cc.y | (int)((t1 - 32u) << 17), d1 * ww.y, Hw, lane, g_qh);
        sweep_comp(t2 >= 32u, cc.z | (int)((t2 - 32u) << 17), d2 * ww.z, Hw, lane, g_qh);
        sweep_comp(t3 >= 32u, cc.w | (int)((t3 - 32u) << 17), d3 * ww.w, Hw, lane, g_qh);
    }

    __syncthreads();
    for (int i = tid; i < C * C; i += 256) {
        float s = 0.0f;
        #pragma unroll
        for (int wg = 0; wg < SPMM_WARPS; wg++) s += Hs[wg][i];
        atomicAdd(&g_H[i], s);
    }
}

// ---------------------------------------------------------------- Sinkhorn: tree sums, 2 syncwarps/iter
__global__ void k_sinkhorn(float* __restrict__ out) {
    __shared__ float ss[C * 33];
    __shared__ float sinv[C];
    int t = threadIdx.x;   // thread t holds column t

    float v[C];
    #pragma unroll
    for (int r = 0; r < C; r++) v[r] = g_H[r * C + t];

    for (int it = 0; it < 3000; it++) {
        // column normalize (local, tree sum)
        float a0 = 0.f, a1 = 0.f, a2 = 0.f, a3 = 0.f;
        #pragma unroll
        for (int r = 0; r < C; r += 4) { a0 += v[r]; a1 += v[r+1]; a2 += v[r+2]; a3 += v[r+3]; }
        float s = (a0 + a1) + (a2 + a3);
        float ic = 1.0f / s;
        #pragma unroll
        for (int r = 0; r < C; r++) { v[r] *= ic; ss[r * 33 + t] = v[r]; }
        __syncwarp();

        // row sum of row t (conflict-free), publish reciprocal
        float b0 = 0.f, b1 = 0.f, b2 = 0.f, b3 = 0.f;
        #pragma unroll
        for (int cc = 0; cc < C; cc += 4) {
            b0 += ss[t * 33 + cc];     b1 += ss[t * 33 + cc + 1];
            b2 += ss[t * 33 + cc + 2]; b3 += ss[t * 33 + cc + 3];
        }
        float s2 = (b0 + b1) + (b2 + b3);
        sinv[t] = 1.0f / s2;
        __syncwarp();

        // row normalize (broadcast reads of sinv)
        #pragma unroll
        for (int r = 0; r < C; r++) v[r] *= sinv[r];

        // both scale factors -> 1 at the fixed point; check every 2 iters
        if (it & 1) {
            float dev = fmaxf(fabsf(s - 1.0f), fabsf(s2 - 1.0f));
            if (it >= 5 && __all_sync(0xFFFFFFFFu, dev < 1e-4f)) break;
        }
    }

    #pragma unroll
    for (int r = 0; r < C; r++) out[r * C + t] = v[r];
}

// ---------------------------------------------------------------- launch
extern "C" void kernel_launch(void* const* d_in, const int* in_sizes, int n_in,
                              void* d_out, int out_size) {
    const int*           ei   = (const int*)d_in[0];      // (2, E): rows then cols
    const float*         ew   = (const float*)d_in[1];    // (E,)
    const float*         x    = (const float*)d_in[2];    // (N, C)
    const float*         y    = (const float*)d_in[3];    // (N, C) one-hot
    const unsigned char* mask = (const unsigned char*)d_in[4];  // (N,) dtype sniffed

    const int* row = ei;
    const int* col = ei + E_EDGES;

    k_init<<<(N_NODES + 255) / 256, 256>>>(mask);
    k_deg<<<(E_EDGES / 4 + 255) / 256, 256>>>((const int4*)row, (const float4*)ew);
    k_node<<<(N_NODES + 255) / 256, 256>>>(x, y, mask);
    k_sweep<<<888, 256>>>((const int4*)row, (const int4*)col, (const float4*)ew);
    k_sinkhorn<<<1, 32>>>((float*)d_out);
}

// round 11
// speedup vs baseline: 1.0928x; 1.0921x over previous
#include <cuda_runtime.h>
#include <cuda_bf16.h>
#include <string.h>

#define N_NODES 100000
#define C 32
#define E_EDGES 3200000
#define SPMM_WARPS 8

// ---- scratch (no allocations allowed) ----
__device__ float         g_deg[N_NODES];
__device__ float         g_ld[N_NODES];         // fp32 dinv, low 6 mantissa bits = (32|label) if masked else 0
__device__ __nv_bfloat16 g_qh[N_NODES * C];     // q[c][j] = dinv[c] * p[c][j], bf16
__device__ int2          g_cmp[E_EDGES];        // compacted kept edges: {col | label<<17, f32 vw}
__device__ float         g_H[C * C];            // unnormalized class-compat accumulator
__device__ int           g_mode;                // mask dtype: 0=u8, 1=i32, 2=f32, 3=bf16
__device__ int           g_cnt;                 // kept-edge count

// ---------------------------------------------------------------- init + mask dtype sniffing (block 0, warp 0)
__global__ void k_init(const unsigned char* __restrict__ m) {
    int i = blockIdx.x * blockDim.x + threadIdx.x;
    if (i < N_NODES) g_deg[i] = 1.0f;          // self-loop weight
    if (i < C * C)   g_H[i]   = 0.0f;
    if (i == 0)      g_cnt    = 0;

    if (blockIdx.x == 0 && threadIdx.x < 32) {
        int lane = threadIdx.x;
        int nz0 = 0, nz1 = 0, nz2 = 0, nz3 = 0, c01 = 0, c3F = 0;
        for (int base = 0; base < 4096; base += 32) {
            unsigned char b = m[base + lane];        // (base+lane)&3 == lane&3
            unsigned nzm = __ballot_sync(0xFFFFFFFFu, b != 0);
            unsigned m01 = __ballot_sync(0xFFFFFFFFu, b == 0x01);
            unsigned m3F = __ballot_sync(0xFFFFFFFFu, b == 0x3F);
            nz0 += __popc(nzm & 0x11111111u);
            nz1 += __popc(nzm & 0x22222222u);
            nz2 += __popc(nzm & 0x44444444u);
            nz3 += __popc(nzm & 0x88888888u);
            c01 += __popc(m01);
            c3F += __popc(m3F);
        }
        if (lane == 0) {
            int mode;
            if (nz1 == 0 && nz2 == 0 && nz3 == 0)
                mode = 1;                                        // int32 (0/1, LE)
            else if (c01 == 0 && c3F > 0)
                mode = (nz0 == 0 && nz1 == 0) ? 2 : 3;           // float32 : bf16
            else
                mode = 0;                                        // uint8 bool
            g_mode = mode;
        }
    }
}

__device__ __forceinline__ bool read_mask(const unsigned char* p, int node, int mode) {
    if (mode == 1) return ((const int*)p)[node] != 0;
    if (mode == 2) return ((const float*)p)[node] != 0.0f;
    if (mode == 3) return ((const unsigned short*)p)[node] != 0;
    return p[node] != 0;
}

// ---------------------------------------------------------------- degree (vectorized)
__global__ void k_deg(const int4* __restrict__ row4, const float4* __restrict__ w4) {
    int e = blockIdx.x * blockDim.x + threadIdx.x;
    if (e < E_EDGES / 4) {
        int4   r = row4[e];
        float4 w = w4[e];
        atomicAdd(&g_deg[r.x], w.x);
        atomicAdd(&g_deg[r.y], w.y);
        atomicAdd(&g_deg[r.z], w.z);
        atomicAdd(&g_deg[r.w], w.w);
    }
}

// ---------------------------------------------------------------- per-node: softmax / mask / dinv / q / self-loop diag
__global__ __launch_bounds__(256) void k_node(const float* __restrict__ x,
                                              const float* __restrict__ y,
                                              const unsigned char* __restrict__ mask) {
    __shared__ float sdiag[C];
    int tid = threadIdx.x;
    if (tid < C) sdiag[tid] = 0.0f;
    __syncthreads();

    int node = blockIdx.x * 256 + tid;
    if (node < N_NODES) {
        int  mode = g_mode;
        bool msk  = read_mask(mask, node, mode);
        float dinv = rsqrtf(g_deg[node]);        // deg >= 1 always
        unsigned packed[16];
        unsigned enc;

        if (msk) {
            // label = argmax of one-hot row (only masked nodes need y)
            const float4* yr = (const float4*)(y + (size_t)node * C);
            int lab = 0;
            #pragma unroll
            for (int i = 0; i < 8; i++) {
                float4 q = yr[i];
                lab = (q.x > 0.5f) ? 4 * i     : lab;
                lab = (q.y > 0.5f) ? 4 * i + 1 : lab;
                lab = (q.z > 0.5f) ? 4 * i + 2 : lab;
                lab = (q.w > 0.5f) ? 4 * i + 3 : lab;
            }
            __nv_bfloat16 h = __float2bfloat16(dinv);
            unsigned hb;
            { unsigned short s; memcpy(&s, &h, 2); hb = s; }
            #pragma unroll
            for (int i = 0; i < 16; i++) {
                unsigned lo = (lab == 2 * i)     ? hb : 0u;
                unsigned hi = (lab == 2 * i + 1) ? hb : 0u;
                packed[i] = lo | (hi << 16);
            }
            atomicAdd(&sdiag[lab], dinv * dinv);             // self-loop diag
            enc = (__float_as_uint(dinv) & ~63u) | 32u | (unsigned)lab;
        } else {
            const float4* xr = (const float4*)(x + (size_t)node * C);
            float v[32];
            #pragma unroll
            for (int i = 0; i < 8; i++) {
                float4 q = xr[i];
                v[4*i] = q.x; v[4*i+1] = q.y; v[4*i+2] = q.z; v[4*i+3] = q.w;
            }
            float m0 = v[0], m1 = v[1], m2 = v[2], m3 = v[3];
            #pragma unroll
            for (int r = 4; r < 32; r += 4) {
                m0 = fmaxf(m0, v[r]); m1 = fmaxf(m1, v[r+1]);
                m2 = fmaxf(m2, v[r+2]); m3 = fmaxf(m3, v[r+3]);
            }
            float mx = fmaxf(fmaxf(m0, m1), fmaxf(m2, m3));
            float a0 = 0.f, a1 = 0.f, a2 = 0.f, a3 = 0.f;
            #pragma unroll
            for (int r = 0; r < 32; r += 4) {
                v[r]   = __expf(v[r]   - mx); a0 += v[r];
                v[r+1] = __expf(v[r+1] - mx); a1 += v[r+1];
                v[r+2] = __expf(v[r+2] - mx); a2 += v[r+2];
                v[r+3] = __expf(v[r+3] - mx); a3 += v[r+3];
            }
            float f = dinv / ((a0 + a1) + (a2 + a3));
            #pragma unroll
            for (int i = 0; i < 16; i++) {
                __nv_bfloat162 hh = __float22bfloat162_rn(make_float2(v[2*i] * f, v[2*i+1] * f));
                memcpy(&packed[i], &hh, 4);
            }
            enc = __float_as_uint(dinv) & ~63u;
        }

        uint4* dst = (uint4*)(g_qh + (size_t)node * C);
        dst[0] = make_uint4(packed[0],  packed[1],  packed[2],  packed[3]);
        dst[1] = make_uint4(packed[4],  packed[5],  packed[6],  packed[7]);
        dst[2] = make_uint4(packed[8],  packed[9],  packed[10], packed[11]);
        dst[3] = make_uint4(packed[12], packed[13], packed[14], packed[15]);
        g_ld[node] = __uint_as_float(enc);
    }
    __syncthreads();
    if (tid < C && sdiag[tid] != 0.0f) atomicAdd(&g_H[tid * C + tid], sdiag[tid]);
}

// ---------------------------------------------------------------- compaction: 8 edges/thread, front-batched gathers (MLP=8)
__global__ __launch_bounds__(256) void k_compact(const int4* __restrict__ row4,
                                                 const int4* __restrict__ col4,
                                                 const float4* __restrict__ w4) {
    int i = blockIdx.x * blockDim.x + threadIdx.x;       // chunk of 8 edges
    int lane = threadIdx.x & 31;
    if (i >= E_EDGES / 8) return;

    int4 ra = row4[2 * i];
    int4 rb = row4[2 * i + 1];
    int rr[8] = {ra.x, ra.y, ra.z, ra.w, rb.x, rb.y, rb.z, rb.w};

    // front-batched MLP=8 gathers
    float d[8];
    #pragma unroll
    for (int k = 0; k < 8; k++) d[k] = g_ld[rr[k]];

    unsigned t[8];
    bool kp[8];
    int cnt = 0;
    #pragma unroll
    for (int k = 0; k < 8; k++) {
        t[k]  = __float_as_uint(d[k]) & 63u;
        kp[k] = t[k] >= 32u;
        cnt  += (int)kp[k];
    }

    // inclusive warp scan
    int ofs = cnt;
    #pragma unroll
    for (int dd = 1; dd < 32; dd <<= 1) {
        int n = __shfl_up_sync(0xFFFFFFFFu, ofs, dd);
        if (lane >= dd) ofs += n;
    }
    int total = __shfl_sync(0xFFFFFFFFu, ofs, 31);
    int basep = 0;
    if (lane == 31 && total) basep = atomicAdd(&g_cnt, total);
    basep = __shfl_sync(0xFFFFFFFFu, basep, 31);
    int p = basep + ofs - cnt;

    if (cnt) {
        int4   ca = col4[2 * i];
        int4   cb = col4[2 * i + 1];
        float4 wa = w4[2 * i];
        float4 wb = w4[2 * i + 1];
        int   cc[8] = {ca.x, ca.y, ca.z, ca.w, cb.x, cb.y, cb.z, cb.w};
        float ww[8] = {wa.x, wa.y, wa.z, wa.w, wb.x, wb.y, wb.z, wb.w};
        #pragma unroll
        for (int k = 0; k < 8; k++)
            if (kp[k])
                g_cmp[p++] = make_int2(cc[k] | (int)((t[k] - 32u) << 17),
                                       __float_as_int(d[k] * ww[k]));
    }
}

// ---------------------------------------------------------------- dense sweep -> 32x32 tile
// Broadcast model, 8-edge sub-batches: shuffles -> 8 independent gathers (MLP=8) -> FMA.
__global__ __launch_bounds__(256) void k_spmm() {
    __shared__ float Hs[SPMM_WARPS][C * C];
    int lane = threadIdx.x & 31;
    int wid  = threadIdx.x >> 5;
    float* Hw = Hs[wid];
    for (int i = lane; i < C * C; i += 32) Hw[i] = 0.0f;
    __syncwarp();

    const unsigned short* qh = (const unsigned short*)g_qh;
    int total = g_cnt;
    int gw = blockIdx.x * SPMM_WARPS + wid;
    int nw = gridDim.x * SPMM_WARPS;

    for (int base = gw * 32; base < total; base += nw * 32) {
        int e = base + lane;
        int2 ent = (e < total) ? g_cmp[e] : make_int2(0, 0);
        if (base + 32 <= total) {
            #pragma unroll
            for (int g = 0; g < 4; g++) {
                int pk[8]; float vv[8]; unsigned qr[8];
                #pragma unroll
                for (int k = 0; k < 8; k++) {
                    pk[k] = __shfl_sync(0xFFFFFFFFu, ent.x, g * 8 + k);
                    vv[k] = __uint_as_float(__shfl_sync(0xFFFFFFFFu, ent.y, g * 8 + k));
                }
                #pragma unroll
                for (int k = 0; k < 8; k++)
                    qr[k] = qh[(pk[k] & 0x1FFFF) * C + lane];     // MLP=8 gather burst
                #pragma unroll
                for (int k = 0; k < 8; k++) {
                    float qf = __uint_as_float(qr[k] << 16);       // bf16 -> f32 via shift
                    Hw[(pk[k] >> 17) * C + lane] += vv[k] * qf;
                }
            }
        } else {
            int cnt = total - base;
            for (int k = 0; k < cnt; k++) {
                int   pk = __shfl_sync(0xFFFFFFFFu, ent.x, k);
                float v  = __uint_as_float(__shfl_sync(0xFFFFFFFFu, ent.y, k));
                float qf = __uint_as_float((unsigned)qh[(pk & 0x1FFFF) * C + lane] << 16);
                Hw[(pk >> 17) * C + lane] += v * qf;
            }
        }
    }

    __syncthreads();
    for (int i = threadIdx.x; i < C * C; i += blockDim.x) {
        float s = 0.0f;
        #pragma unroll
        for (int wg = 0; wg < SPMM_WARPS; wg++) s += Hs[wg][i];
        atomicAdd(&g_H[i], s);
    }
}

// ---------------------------------------------------------------- Sinkhorn: tree sums, 2 syncwarps/iter
__global__ void k_sinkhorn(float* __restrict__ out) {
    __shared__ float ss[C * 33];
    __shared__ float sinv[C];
    int t = threadIdx.x;   // thread t holds column t

    float v[C];
    #pragma unroll
    for (int r = 0; r < C; r++) v[r] = g_H[r * C + t];

    for (int it = 0; it < 3000; it++) {
        // column normalize (local, tree sum)
        float a0 = 0.f, a1 = 0.f, a2 = 0.f, a3 = 0.f;
        #pragma unroll
        for (int r = 0; r < C; r += 4) { a0 += v[r]; a1 += v[r+1]; a2 += v[r+2]; a3 += v[r+3]; }
        float s = (a0 + a1) + (a2 + a3);
        float ic = 1.0f / s;
        #pragma unroll
        for (int r = 0; r < C; r++) { v[r] *= ic; ss[r * 33 + t] = v[r]; }
        __syncwarp();

        // row sum of row t (conflict-free), publish reciprocal
        float b0 = 0.f, b1 = 0.f, b2 = 0.f, b3 = 0.f;
        #pragma unroll
        for (int cc = 0; cc < C; cc += 4) {
            b0 += ss[t * 33 + cc];     b1 += ss[t * 33 + cc + 1];
            b2 += ss[t * 33 + cc + 2]; b3 += ss[t * 33 + cc + 3];
        }
        float s2 = (b0 + b1) + (b2 + b3);
        sinv[t] = 1.0f / s2;
        __syncwarp();

        // row normalize (broadcast reads of sinv)
        #pragma unroll
        for (int r = 0; r < C; r++) v[r] *= sinv[r];

        // both scale factors -> 1 at the fixed point; check every 2 iters
        if (it & 1) {
            float dev = fmaxf(fabsf(s - 1.0f), fabsf(s2 - 1.0f));
            if (it >= 5 && __all_sync(0xFFFFFFFFu, dev < 1e-4f)) break;
        }
    }

    #pragma unroll
    for (int r = 0; r < C; r++) out[r * C + t] = v[r];
}

// ---------------------------------------------------------------- launch
extern "C" void kernel_launch(void* const* d_in, const int* in_sizes, int n_in,
                              void* d_out, int out_size) {
    const int*           ei   = (const int*)d_in[0];      // (2, E): rows then cols
    const float*         ew   = (const float*)d_in[1];    // (E,)
    const float*         x    = (const float*)d_in[2];    // (N, C)
    const float*         y    = (const float*)d_in[3];    // (N, C) one-hot
    const unsigned char* mask = (const unsigned char*)d_in[4];  // (N,) dtype sniffed

    const int* row = ei;
    const int* col = ei + E_EDGES;

    k_init<<<(N_NODES + 255) / 256, 256>>>(mask);
    k_deg<<<(E_EDGES / 4 + 255) / 256, 256>>>((const int4*)row, (const float4*)ew);
    k_node<<<(N_NODES + 255) / 256, 256>>>(x, y, mask);
    k_compact<<<(E_EDGES / 8 + 255) / 256, 256>>>((const int4*)row, (const int4*)col, (const float4*)ew);
    k_spmm<<<1036, 256>>>();
    k_sinkhorn<<<1, 32>>>((float*)d_out);
}